// round 14
// baseline (speedup 1.0000x reference)
#include <cuda_runtime.h>
#include <cuda_bf16.h>
#include <cuda_fp16.h>
#include <math.h>

// ---------------------------------------------------------------------------
// RawSequenceEncoder: compress -> in-proj -> 4x conv blocks -> final LN
// B=32, S=4096, D=256, T=256, NB=4, K=5. M = 8192 rows.
// R14: single-pass fp16 mma.sync GEMMs (fp32 acc). Square GEMMs now use a
// 64x64 tile (grid 512 CTAs -> ~3.5 CTAs/SM; R13's 256-CTA grid was
// grid-starved at occ 20%). Gated GEMMs keep the 64x128 tile (gate/value
// pairing needs 128 B-rows per CTA).
// ---------------------------------------------------------------------------

#define BATCH 32
#define SEQ   4096
#define DMODEL 256
#define TLEN  256
#define NBLK  4
#define KSZ   5
#define MROWS (BATCH * TLEN)   // 8192
#define EPSV  1e-5f
#define KDIM  256

// ------------------------- scratch (static, no allocs) ---------------------
static __device__ __half g_a[MROWS * KDIM];   // activations (compress / lnconv out)
static __device__ __half g_c[MROWS * KDIM];   // gated activation out
#define WOFF_IN    0
#define WOFF_WOUT(i) (65536 + (i) * 65536)
#define WOFF_GATE(i) (65536 * 5 + (i) * 131072)
#define WTOT (65536 * 5 + 131072 * 4)
static __device__ __half g_w[WTOT];           // prepped weights [N,K] fp16
static __device__ float g_h[MROWS * DMODEL];
static __device__ int   g_len[BATCH];

// ------------------------- PTX helpers (sm_80-era only) ---------------------
__device__ __forceinline__ unsigned smem_u32(const void* p) {
    unsigned a;
    asm("{ .reg .u64 t; cvta.to.shared.u64 t, %1; cvt.u32.u64 %0, t; }"
        : "=r"(a) : "l"(p));
    return a;
}
#define CP_ASYNC16(dst, src) \
    asm volatile("cp.async.cg.shared.global [%0], [%1], 16;" :: "r"(dst), "l"(src))
#define CP_COMMIT() asm volatile("cp.async.commit_group;" ::: "memory")
#define CP_WAIT(N)  asm volatile("cp.async.wait_group %0;" :: "n"(N) : "memory")

__device__ __forceinline__ void ldsm_x4(unsigned* r, unsigned addr) {
    asm volatile("ldmatrix.sync.aligned.m8n8.x4.shared.b16 {%0,%1,%2,%3}, [%4];"
                 : "=r"(r[0]), "=r"(r[1]), "=r"(r[2]), "=r"(r[3]) : "r"(addr));
}
__device__ __forceinline__ void ldsm_x2(unsigned* r, unsigned addr) {
    asm volatile("ldmatrix.sync.aligned.m8n8.x2.shared.b16 {%0,%1}, [%2];"
                 : "=r"(r[0]), "=r"(r[1]) : "r"(addr));
}
__device__ __forceinline__ void mma16816h(float* d, const unsigned* a, const unsigned* b) {
    asm volatile("mma.sync.aligned.m16n8k16.row.col.f32.f16.f16.f32 "
                 "{%0,%1,%2,%3}, {%4,%5,%6,%7}, {%8,%9}, {%0,%1,%2,%3};"
                 : "+f"(d[0]), "+f"(d[1]), "+f"(d[2]), "+f"(d[3])
                 : "r"(a[0]), "r"(a[1]), "r"(a[2]), "r"(a[3]),
                   "r"(b[0]), "r"(b[1]));
}

// ------------------------- fused mask detect + lengths ----------------------
__global__ __launch_bounds__(256)
void lengths_kernel(const unsigned char* __restrict__ maskp) {
    __shared__ float sh[8];
    __shared__ int sflags;   // bit0 = saw byte>1 (f32), bit1 = nonzero at i%4!=0 (u8)
    int b = blockIdx.x;
    if (threadIdx.x == 0) sflags = 0;
    __syncthreads();

    const unsigned* pw = (const unsigned*)maskp;
    const int nwords = (BATCH * SEQ) / 4;   // safe lower bound across dtypes
    int fl = 0;
    for (int i = threadIdx.x; i < nwords; i += 256) {
        unsigned w = pw[i];
        unsigned b0 = w & 0xFF, b1 = (w >> 8) & 0xFF,
                 b2 = (w >> 16) & 0xFF, b3 = w >> 24;
        if (b0 > 1 || b1 > 1 || b2 > 1 || b3 > 1) fl |= 1;
        if (w & 0xFFFFFF00u) fl |= 2;
    }
    if (__any_sync(0xffffffffu, fl & 1)) fl |= 1;
    if (__any_sync(0xffffffffu, fl & 2)) fl |= 2;
    if ((threadIdx.x & 31) == 0 && fl) atomicOr(&sflags, fl);
    __syncthreads();
    int kind = (sflags & 1) ? 2 : ((sflags & 2) ? 0 : 1); // 2=f32, 0=u8, 1=i32

    float local = 0.0f;
    if (kind == 0) {
        const unsigned char* p = maskp + (size_t)b * SEQ;
        for (int i = threadIdx.x; i < SEQ; i += 256) local += (float)p[i];
    } else if (kind == 1) {
        const int* p = (const int*)maskp + (size_t)b * SEQ;
        for (int i = threadIdx.x; i < SEQ; i += 256) local += (float)p[i];
    } else {
        const float* p = (const float*)maskp + (size_t)b * SEQ;
        for (int i = threadIdx.x; i < SEQ; i += 256) local += p[i];
    }
    int lane = threadIdx.x & 31, w = threadIdx.x >> 5;
    #pragma unroll
    for (int o = 16; o > 0; o >>= 1) local += __shfl_down_sync(0xffffffffu, local, o);
    if (lane == 0) sh[w] = local;
    __syncthreads();
    if (threadIdx.x == 0) {
        float tot = 0.0f;
        #pragma unroll
        for (int i = 0; i < 8; i++) tot += sh[i];
        g_len[b] = (int)lrintf(tot);
    }
}

// ------------------------- compress -> fp16 ----------------------------------
__global__ void compress_kernel(const float* __restrict__ x) {
    int b = blockIdx.y;
    int t = blockIdx.x * 2 + (threadIdx.x >> 6);
    int lane = threadIdx.x & 63;
    int L = g_len[b];
    float Lf  = (float)L;
    float src = ((float)t + 0.5f) * (Lf * (1.0f / (float)TLEN)) - 0.5f;
    float hi  = fmaxf(Lf - 1.0f, 0.0f);
    src = fminf(fmaxf(src, 0.0f), hi);
    int   i0 = (int)floorf(src);
    int   i1 = min(i0 + 1, max(L - 1, 0));
    float w  = src - (float)i0;
    const float4* r0 = (const float4*)(x + ((size_t)b * SEQ + i0) * DMODEL);
    const float4* r1 = (const float4*)(x + ((size_t)b * SEQ + i1) * DMODEL);
    float4 v0 = r0[lane], v1 = r1[lane];
    float o[4];
    o[0] = (1.0f - w) * v0.x + w * v1.x;
    o[1] = (1.0f - w) * v0.y + w * v1.y;
    o[2] = (1.0f - w) * v0.z + w * v1.z;
    o[3] = (1.0f - w) * v0.w + w * v1.w;
    size_t base = ((size_t)(b * TLEN + t)) * DMODEL + lane * 4;
    __half2 p0, p1;
    p0.x = __float2half_rn(o[0]); p0.y = __float2half_rn(o[1]);
    p1.x = __float2half_rn(o[2]); p1.y = __float2half_rn(o[3]);
    *(__half2*)(g_a + base)     = p0;
    *(__half2*)(g_a + base + 2) = p1;
}

// ------------------------- fused weight prep (ONE launch) -------------------
__global__ void prep_all_w_kernel(const float* __restrict__ in_w,
                                  const float* __restrict__ wout_w,
                                  const float* __restrict__ win_w,
                                  __half* __restrict__ wdst) {
    __shared__ float t[32][33];
    int bid = blockIdx.x;
    const float* W;
    int srcld, gated, tile;
    size_t dsto;
    if (bid < 64) {
        W = in_w; srcld = 256; gated = 0; dsto = WOFF_IN; tile = bid;
    } else if (bid < 320) {
        int tt = bid - 64, i = tt >> 6;
        W = wout_w + (size_t)i * 65536; srcld = 256; gated = 0;
        dsto = WOFF_WOUT(i); tile = tt & 63;
    } else {
        int tt = bid - 320, i = tt >> 7;
        W = win_w + (size_t)i * 131072; srcld = 512; gated = 1;
        dsto = WOFF_GATE(i); tile = tt & 127;
    }
    int kx = (tile & 7) * 32, py = (tile >> 3) * 32;
    int tx = threadIdx.x, ty = threadIdx.y;
    int p = py + tx;
    int srccol;
    if (gated) {
        int j = p >> 7, r5 = p & 127;
        srccol = j * 64 + (r5 & 63) + ((r5 & 64) ? 256 : 0);
    } else srccol = p;
    t[ty][tx] = W[(size_t)(kx + ty) * srcld + srccol];
    __syncthreads();
    int pp = py + ty, k = kx + tx;
    wdst[dsto + (size_t)pp * KDIM + k] = __float2half_rn(t[tx][ty]);
}

// ------------------------- fused LN + conv -> fp16 --------------------------
__global__ __launch_bounds__(256)
void lnconv_kernel(const float* __restrict__ h,
                   const float* __restrict__ g, const float* __restrict__ bta,
                   const float* __restrict__ w, const float* __restrict__ cbias,
                   __half* __restrict__ oh) {
    __shared__ float sh[36][DMODEL];
    int b = blockIdx.y;
    int t0 = blockIdx.x * 32;
    int warp = threadIdx.x >> 5, lane = threadIdx.x & 31;

    for (int r = warp; r < 36; r += 8) {
        int t = t0 - 2 + r;
        if (t < 0 || t >= TLEN) {
            float4 z = make_float4(0.f, 0.f, 0.f, 0.f);
            ((float4*)sh[r])[lane * 2]     = z;
            ((float4*)sh[r])[lane * 2 + 1] = z;
        } else {
            const float4* p = (const float4*)(h + ((size_t)(b * TLEN + t)) * DMODEL);
            float4 v0 = p[lane * 2], v1 = p[lane * 2 + 1];
            float s  = v0.x + v0.y + v0.z + v0.w + v1.x + v1.y + v1.z + v1.w;
            float sq = v0.x*v0.x + v0.y*v0.y + v0.z*v0.z + v0.w*v0.w
                     + v1.x*v1.x + v1.y*v1.y + v1.z*v1.z + v1.w*v1.w;
            #pragma unroll
            for (int o = 16; o > 0; o >>= 1) {
                s  += __shfl_xor_sync(0xffffffffu, s,  o);
                sq += __shfl_xor_sync(0xffffffffu, sq, o);
            }
            float mu  = s  * (1.0f / (float)DMODEL);
            float var = sq * (1.0f / (float)DMODEL) - mu * mu;
            float rs  = rsqrtf(var + EPSV);
            const float4* gp = (const float4*)g;
            const float4* bp = (const float4*)bta;
            float4 g0 = gp[lane * 2], g1 = gp[lane * 2 + 1];
            float4 b0 = bp[lane * 2], b1 = bp[lane * 2 + 1];
            float4 o0, o1;
            o0.x = (v0.x - mu) * rs * g0.x + b0.x;
            o0.y = (v0.y - mu) * rs * g0.y + b0.y;
            o0.z = (v0.z - mu) * rs * g0.z + b0.z;
            o0.w = (v0.w - mu) * rs * g0.w + b0.w;
            o1.x = (v1.x - mu) * rs * g1.x + b1.x;
            o1.y = (v1.y - mu) * rs * g1.y + b1.y;
            o1.z = (v1.z - mu) * rs * g1.z + b1.z;
            o1.w = (v1.w - mu) * rs * g1.w + b1.w;
            ((float4*)sh[r])[lane * 2]     = o0;
            ((float4*)sh[r])[lane * 2 + 1] = o1;
        }
    }
    __syncthreads();

    int d = threadIdx.x;
    float w0 = w[d * KSZ + 0], w1 = w[d * KSZ + 1], w2 = w[d * KSZ + 2];
    float w3 = w[d * KSZ + 3], w4 = w[d * KSZ + 4];
    float cb = cbias[d];
    float acc[32];
    #pragma unroll
    for (int t = 0; t < 32; t++) {
        float a = cb;
        a = fmaf(w0, sh[t    ][d], a);
        a = fmaf(w1, sh[t + 1][d], a);
        a = fmaf(w2, sh[t + 2][d], a);
        a = fmaf(w3, sh[t + 3][d], a);
        a = fmaf(w4, sh[t + 4][d], a);
        acc[t] = a;
    }
    __syncthreads();
    #pragma unroll
    for (int t = 0; t < 32; t++) sh[t][d] = acc[t];
    __syncthreads();

    size_t rowbase = (size_t)(b * TLEN + t0);
    for (int p = threadIdx.x; p < 32 * 128; p += 256) {
        int r = p >> 7, dp = (p & 127) * 2;
        __half2 ph;
        ph.x = __float2half_rn(sh[r][dp]);
        ph.y = __float2half_rn(sh[r][dp + 1]);
        *(__half2*)(oh + (rowbase + r) * DMODEL + dp) = ph;
    }
}

// ------------------------- warp-per-row final layer norm --------------------
__global__ void ln_warp_kernel(const float* __restrict__ in,
                               const float* __restrict__ g,
                               const float* __restrict__ bta,
                               float* __restrict__ out) {
    int warp = threadIdx.x >> 5, lane = threadIdx.x & 31;
    int m = blockIdx.x * 8 + warp;
    const float4* p = (const float4*)(in + (size_t)m * DMODEL);
    float4 v0 = p[lane * 2], v1 = p[lane * 2 + 1];
    float s  = v0.x + v0.y + v0.z + v0.w + v1.x + v1.y + v1.z + v1.w;
    float sq = v0.x*v0.x + v0.y*v0.y + v0.z*v0.z + v0.w*v0.w
             + v1.x*v1.x + v1.y*v1.y + v1.z*v1.z + v1.w*v1.w;
    #pragma unroll
    for (int o = 16; o > 0; o >>= 1) {
        s  += __shfl_xor_sync(0xffffffffu, s,  o);
        sq += __shfl_xor_sync(0xffffffffu, sq, o);
    }
    float mu  = s  * (1.0f / (float)DMODEL);
    float var = sq * (1.0f / (float)DMODEL) - mu * mu;
    float rs  = rsqrtf(var + EPSV);
    const float4* gp = (const float4*)g;
    const float4* bp = (const float4*)bta;
    float4 g0 = gp[lane * 2], g1 = gp[lane * 2 + 1];
    float4 b0 = bp[lane * 2], b1 = bp[lane * 2 + 1];
    float4 o0, o1;
    o0.x = (v0.x - mu) * rs * g0.x + b0.x;
    o0.y = (v0.y - mu) * rs * g0.y + b0.y;
    o0.z = (v0.z - mu) * rs * g0.z + b0.z;
    o0.w = (v0.w - mu) * rs * g0.w + b0.w;
    o1.x = (v1.x - mu) * rs * g1.x + b1.x;
    o1.y = (v1.y - mu) * rs * g1.y + b1.y;
    o1.z = (v1.z - mu) * rs * g1.z + b1.z;
    o1.w = (v1.w - mu) * rs * g1.w + b1.w;
    ((float4*)(out + (size_t)m * DMODEL))[lane * 2]     = o0;
    ((float4*)(out + (size_t)m * DMODEL))[lane * 2 + 1] = o1;
}

// ------------------------- fp16 mma.sync GEMM (templated N-tile) ------------
// Per CTA: D[64, 32*NT] = A[64,256] @ Bprep[32*NT rows,256]^T, fp16/fp32 acc.
// NT = n-tiles (8 cols) per warp: NT=2 -> 64-wide tile; NT=4 -> 128-wide.
// MODE 0: outf = D + bias;  MODE 1: += resid;  MODE 2 (NT=4 only): gated
// sigmoid*gelu -> fp16 (gate = D cols 0-63, value = D cols 64-127).
// smem: 4 stages x {A:64rows, B:32*NT rows} x 80 B rows.
#define TS4   80
#define A_T4  (64 * TS4)             // 5120

template<int MODE, int NT>
__global__ __launch_bounds__(256, 3)
void gemm_mma_kernel(const __half* __restrict__ A,
                     const __half* __restrict__ B,
                     const float* __restrict__ bias, const float* __restrict__ resid,
                     float* __restrict__ outf,
                     __half* __restrict__ outh) {
    constexpr int BROWS = 32 * NT;
    constexpr int B_T = BROWS * TS4;
    constexpr int ST = A_T4 + B_T;
    constexpr int NTILE = 32 * NT;       // output cols per CTA
    constexpr int SEPI = NTILE + 4;      // epilogue smem stride (floats)

    extern __shared__ char sm[];
    unsigned sbase = smem_u32(sm);
    const int tid = threadIdx.x, wid = tid >> 5, lane = tid & 31;
    const int m0 = blockIdx.y * 64;
    const int nb = blockIdx.x;
    const int n0p = nb * NTILE;

    const char* A8 = (const char*)A + (size_t)m0 * 512;
    const char* B8 = (const char*)B + (size_t)n0p * 512;

    auto load_stage = [&](int s, int k0) {
        unsigned dst0 = sbase + s * ST;
        int kbyte = k0 * 2;
        {   // A: 64 rows x 4 x 16B chunks = 256 = one pass
            int row = tid >> 2, c16 = (tid & 3) * 16;
            CP_ASYNC16(dst0 + row * TS4 + c16,
                       A8 + (size_t)row * 512 + kbyte + c16);
        }
        #pragma unroll
        for (int i = tid; i < BROWS * 4; i += 256) {
            int row = i >> 2, c16 = (i & 3) * 16;
            CP_ASYNC16(dst0 + A_T4 + row * TS4 + c16,
                       B8 + (size_t)row * 512 + kbyte + c16);
        }
        CP_COMMIT();
    };

    load_stage(0, 0);
    load_stage(1, 32);
    load_stage(2, 64);

    const int warpM = wid & 1, warpN = wid >> 1;  // 2 x 4 warps
    float acc[2][NT][4];
    #pragma unroll
    for (int mt = 0; mt < 2; mt++)
        #pragma unroll
        for (int nt = 0; nt < NT; nt++)
            #pragma unroll
            for (int e = 0; e < 4; e++) acc[mt][nt][e] = 0.0f;

    const unsigned a_row = warpM * 32 + (lane & 15);
    const unsigned a_cofs = ((lane >> 4) << 3) * 2;          // 0 or 16 bytes
    const unsigned b_row = warpN * (NT * 8) + (lane & 7);
    const unsigned b_cofs = (((lane >> 3) & 1) << 3) * 2;    // 0 or 16 bytes

    #pragma unroll 1
    for (int i = 0; i < 8; i++) {
        if (i < 6) { CP_WAIT(2); } else if (i == 6) { CP_WAIT(1); } else { CP_WAIT(0); }
        __syncthreads();
        if (i + 3 < 8) load_stage((i + 3) & 3, (i + 3) * 32);
        unsigned st  = sbase + (i & 3) * ST;
        unsigned ab  = st;
        unsigned bb  = st + A_T4;
        #pragma unroll
        for (int ks = 0; ks < 2; ks++) {
            unsigned aoff = a_row * TS4 + ks * 32 + a_cofs;
            unsigned boff = b_row * TS4 + ks * 32 + b_cofs;
            unsigned af[2][4];
            unsigned bf[NT][2];
            ldsm_x4(af[0], ab + aoff);
            ldsm_x4(af[1], ab + aoff + 16 * TS4);
            #pragma unroll
            for (int nt = 0; nt < NT; nt++)
                ldsm_x2(bf[nt], bb + boff + nt * 8 * TS4);
            #pragma unroll
            for (int nt = 0; nt < NT; nt++)
                #pragma unroll
                for (int mt = 0; mt < 2; mt++)
                    mma16816h(acc[mt][nt], af[mt], bf[nt]);
        }
    }
    __syncthreads();   // all stages consumed; reuse smem for epilogue

    // ---- epilogue: stage D through smem (64 rows x SEPI-float stride) ----
    float* smf = (float*)sm;
    #pragma unroll
    for (int mt = 0; mt < 2; mt++) {
        #pragma unroll
        for (int nt = 0; nt < NT; nt++) {
            int r = warpM * 32 + mt * 16 + (lane >> 2);
            int c = warpN * (NT * 8) + nt * 8 + (lane & 3) * 2;
            smf[r * SEPI + c]           = acc[mt][nt][0];
            smf[r * SEPI + c + 1]       = acc[mt][nt][1];
            smf[(r + 8) * SEPI + c]     = acc[mt][nt][2];
            smf[(r + 8) * SEPI + c + 1] = acc[mt][nt][3];
        }
    }
    __syncthreads();

    if (MODE == 2) {   // NT == 4 only
        const int outn0 = nb * 64;
        for (int i = tid; i < 64 * 32; i += 256) {
            int row = i >> 5, c2 = (i & 31) * 2;
            float gg0 = smf[row * SEPI + c2]     + bias[outn0 + c2];
            float gg1 = smf[row * SEPI + c2 + 1] + bias[outn0 + c2 + 1];
            float vv0 = smf[row * SEPI + 64 + c2]     + bias[256 + outn0 + c2];
            float vv1 = smf[row * SEPI + 64 + c2 + 1] + bias[256 + outn0 + c2 + 1];
            float s0 = 1.0f / (1.0f + expf(-gg0));
            float s1 = 1.0f / (1.0f + expf(-gg1));
            float e0 = 0.5f * vv0 * (1.0f + erff(vv0 * 0.7071067811865476f));
            float e1 = 0.5f * vv1 * (1.0f + erff(vv1 * 0.7071067811865476f));
            __half2 ph;
            ph.x = __float2half_rn(s0 * e0);
            ph.y = __float2half_rn(s1 * e1);
            size_t ob = (size_t)(m0 + row) * DMODEL + outn0 + c2;
            *(__half2*)(outh + ob) = ph;
        }
    } else {
        constexpr int CN4 = NTILE / 4;   // float4s per row
        for (int i = tid; i < 64 * CN4; i += 256) {
            int row = i / CN4, c4 = (i % CN4) * 4;
            float4 o;
            o.x = smf[row * SEPI + c4]     + bias[n0p + c4];
            o.y = smf[row * SEPI + c4 + 1] + bias[n0p + c4 + 1];
            o.z = smf[row * SEPI + c4 + 2] + bias[n0p + c4 + 2];
            o.w = smf[row * SEPI + c4 + 3] + bias[n0p + c4 + 3];
            size_t base = (size_t)(m0 + row) * DMODEL + n0p + c4;
            if (MODE == 1) {
                float4 rr = *(const float4*)(resid + base);
                o.x += rr.x; o.y += rr.y; o.z += rr.z; o.w += rr.w;
            }
            *(float4*)(outf + base) = o;
        }
    }
}

#define GEMM_SMEM_S (4 * (A_T4 + 64 * TS4))    // 40960 (NT=2)
#define GEMM_SMEM_G (4 * (A_T4 + 128 * TS4))   // 61440 (NT=4)

// ------------------------- mask tail ----------------------------------------
__global__ void fill_ones_kernel(float* __restrict__ p, int n) {
    int i = blockIdx.x * blockDim.x + threadIdx.x;
    if (i < n) p[i] = 1.0f;
}

// ---------------------------------------------------------------------------
extern "C" void kernel_launch(void* const* d_in, const int* in_sizes, int n_in,
                              void* d_out, int out_size) {
    const float* x      = (const float*)d_in[0];
    const void*  mask   = d_in[1];
    const float* in_w   = (const float*)d_in[2];
    const float* in_b   = (const float*)d_in[3];
    const float* ln_g   = (const float*)d_in[4];
    const float* ln_b   = (const float*)d_in[5];
    const float* dw_w   = (const float*)d_in[6];
    const float* dw_b   = (const float*)d_in[7];
    const float* win_w  = (const float*)d_in[8];
    const float* win_b  = (const float*)d_in[9];
    const float* wout_w = (const float*)d_in[10];
    const float* wout_b = (const float*)d_in[11];
    const float* fn_g   = (const float*)d_in[12];
    const float* fn_b   = (const float*)d_in[13];
    float* out = (float*)d_out;

    __half *a, *c, *w;
    float *h;
    cudaGetSymbolAddress((void**)&a, g_a);
    cudaGetSymbolAddress((void**)&c, g_c);
    cudaGetSymbolAddress((void**)&w, g_w);
    cudaGetSymbolAddress((void**)&h, g_h);

    cudaFuncSetAttribute((const void*)gemm_mma_kernel<0, 2>,
        cudaFuncAttributeMaxDynamicSharedMemorySize, GEMM_SMEM_S);
    cudaFuncSetAttribute((const void*)gemm_mma_kernel<1, 2>,
        cudaFuncAttributeMaxDynamicSharedMemorySize, GEMM_SMEM_S);
    cudaFuncSetAttribute((const void*)gemm_mma_kernel<2, 4>,
        cudaFuncAttributeMaxDynamicSharedMemorySize, GEMM_SMEM_G);

    // 1) mask dtype detection + lengths (one launch)
    lengths_kernel<<<BATCH, 256>>>((const unsigned char*)mask);

    // 2) fused weight prep (one launch: 64 + 4*64 + 4*128 = 832 blocks)
    prep_all_w_kernel<<<832, dim3(32, 32)>>>(in_w, wout_w, win_w, w);

    // 3) compress to fp16
    compress_kernel<<<dim3(TLEN / 2, BATCH), 128>>>(x);

    // 4) input projection: h = xc @ in_w + in_b   (grid 4 x 128 = 512 CTAs)
    gemm_mma_kernel<0, 2><<<dim3(4, 128), 256, GEMM_SMEM_S>>>(
        a, w + WOFF_IN, in_b, nullptr, h, nullptr);

    // 5) conv blocks
    for (int i = 0; i < NBLK; i++) {
        lnconv_kernel<<<dim3(TLEN / 32, BATCH), 256>>>(
            h, ln_g + i * DMODEL, ln_b + i * DMODEL,
            dw_w + (size_t)i * DMODEL * KSZ, dw_b + i * DMODEL, a);
        gemm_mma_kernel<2, 4><<<dim3(4, 128), 256, GEMM_SMEM_G>>>(
            a, w + WOFF_GATE(i), win_b + (size_t)i * 2 * DMODEL, nullptr,
            nullptr, c);
        gemm_mma_kernel<1, 2><<<dim3(4, 128), 256, GEMM_SMEM_S>>>(
            c, w + WOFF_WOUT(i), wout_b + i * DMODEL, h, h, nullptr);
    }

    // 6) final layer norm -> out
    ln_warp_kernel<<<MROWS / 8, 256>>>(h, fn_g, fn_b, out);

    // 7) comp_mask tail (all True -> 1.0f) if present in out buffer
    int main_elems = MROWS * DMODEL;
    int extra = out_size - main_elems;
    if (extra > 0)
        fill_ones_kernel<<<(extra + 255) / 256, 256>>>(out + main_elems, extra);
}

// round 15
// speedup vs baseline: 1.0278x; 1.0278x over previous
#include <cuda_runtime.h>
#include <cuda_bf16.h>
#include <cuda_fp16.h>
#include <math.h>

// ---------------------------------------------------------------------------
// RawSequenceEncoder: compress -> in-proj -> 4x conv blocks -> final LN
// B=32, S=4096, D=256, T=256, NB=4, K=5. M = 8192 rows.
// R15: staged-bytes model. Squares keep R13's 64x128 config (best measured).
// Gated GEMM rebuilt as BM=128 x BROWS=256, 512 threads: cuts its cp.async
// staged traffic from ~324 KB/SM to ~187 KB/SM (A re-read 8x -> 2x).
// ---------------------------------------------------------------------------

#define BATCH 32
#define SEQ   4096
#define DMODEL 256
#define TLEN  256
#define NBLK  4
#define KSZ   5
#define MROWS (BATCH * TLEN)   // 8192
#define EPSV  1e-5f
#define KDIM  256

// ------------------------- scratch (static, no allocs) ---------------------
static __device__ __half g_a[MROWS * KDIM];   // activations (compress / lnconv out)
static __device__ __half g_c[MROWS * KDIM];   // gated activation out
#define WOFF_IN    0
#define WOFF_WOUT(i) (65536 + (i) * 65536)
#define WOFF_GATE(i) (65536 * 5 + (i) * 131072)
#define WTOT (65536 * 5 + 131072 * 4)
static __device__ __half g_w[WTOT];           // prepped weights [N,K] fp16
static __device__ float g_h[MROWS * DMODEL];
static __device__ int   g_len[BATCH];

// ------------------------- PTX helpers (sm_80-era only) ---------------------
__device__ __forceinline__ unsigned smem_u32(const void* p) {
    unsigned a;
    asm("{ .reg .u64 t; cvta.to.shared.u64 t, %1; cvt.u32.u64 %0, t; }"
        : "=r"(a) : "l"(p));
    return a;
}
#define CP_ASYNC16(dst, src) \
    asm volatile("cp.async.cg.shared.global [%0], [%1], 16;" :: "r"(dst), "l"(src))
#define CP_COMMIT() asm volatile("cp.async.commit_group;" ::: "memory")
#define CP_WAIT(N)  asm volatile("cp.async.wait_group %0;" :: "n"(N) : "memory")

__device__ __forceinline__ void ldsm_x4(unsigned* r, unsigned addr) {
    asm volatile("ldmatrix.sync.aligned.m8n8.x4.shared.b16 {%0,%1,%2,%3}, [%4];"
                 : "=r"(r[0]), "=r"(r[1]), "=r"(r[2]), "=r"(r[3]) : "r"(addr));
}
__device__ __forceinline__ void ldsm_x2(unsigned* r, unsigned addr) {
    asm volatile("ldmatrix.sync.aligned.m8n8.x2.shared.b16 {%0,%1}, [%2];"
                 : "=r"(r[0]), "=r"(r[1]) : "r"(addr));
}
__device__ __forceinline__ void mma16816h(float* d, const unsigned* a, const unsigned* b) {
    asm volatile("mma.sync.aligned.m16n8k16.row.col.f32.f16.f16.f32 "
                 "{%0,%1,%2,%3}, {%4,%5,%6,%7}, {%8,%9}, {%0,%1,%2,%3};"
                 : "+f"(d[0]), "+f"(d[1]), "+f"(d[2]), "+f"(d[3])
                 : "r"(a[0]), "r"(a[1]), "r"(a[2]), "r"(a[3]),
                   "r"(b[0]), "r"(b[1]));
}

// ------------------------- fused mask detect + lengths ----------------------
__global__ __launch_bounds__(256)
void lengths_kernel(const unsigned char* __restrict__ maskp) {
    __shared__ float sh[8];
    __shared__ int sflags;   // bit0 = saw byte>1 (f32), bit1 = nonzero at i%4!=0 (u8)
    int b = blockIdx.x;
    if (threadIdx.x == 0) sflags = 0;
    __syncthreads();

    const unsigned* pw = (const unsigned*)maskp;
    const int nwords = (BATCH * SEQ) / 4;   // safe lower bound across dtypes
    int fl = 0;
    for (int i = threadIdx.x; i < nwords; i += 256) {
        unsigned w = pw[i];
        unsigned b0 = w & 0xFF, b1 = (w >> 8) & 0xFF,
                 b2 = (w >> 16) & 0xFF, b3 = w >> 24;
        if (b0 > 1 || b1 > 1 || b2 > 1 || b3 > 1) fl |= 1;
        if (w & 0xFFFFFF00u) fl |= 2;
    }
    if (__any_sync(0xffffffffu, fl & 1)) fl |= 1;
    if (__any_sync(0xffffffffu, fl & 2)) fl |= 2;
    if ((threadIdx.x & 31) == 0 && fl) atomicOr(&sflags, fl);
    __syncthreads();
    int kind = (sflags & 1) ? 2 : ((sflags & 2) ? 0 : 1); // 2=f32, 0=u8, 1=i32

    float local = 0.0f;
    if (kind == 0) {
        const unsigned char* p = maskp + (size_t)b * SEQ;
        for (int i = threadIdx.x; i < SEQ; i += 256) local += (float)p[i];
    } else if (kind == 1) {
        const int* p = (const int*)maskp + (size_t)b * SEQ;
        for (int i = threadIdx.x; i < SEQ; i += 256) local += (float)p[i];
    } else {
        const float* p = (const float*)maskp + (size_t)b * SEQ;
        for (int i = threadIdx.x; i < SEQ; i += 256) local += p[i];
    }
    int lane = threadIdx.x & 31, w = threadIdx.x >> 5;
    #pragma unroll
    for (int o = 16; o > 0; o >>= 1) local += __shfl_down_sync(0xffffffffu, local, o);
    if (lane == 0) sh[w] = local;
    __syncthreads();
    if (threadIdx.x == 0) {
        float tot = 0.0f;
        #pragma unroll
        for (int i = 0; i < 8; i++) tot += sh[i];
        g_len[b] = (int)lrintf(tot);
    }
}

// ------------------------- compress -> fp16 ----------------------------------
__global__ void compress_kernel(const float* __restrict__ x) {
    int b = blockIdx.y;
    int t = blockIdx.x * 2 + (threadIdx.x >> 6);
    int lane = threadIdx.x & 63;
    int L = g_len[b];
    float Lf  = (float)L;
    float src = ((float)t + 0.5f) * (Lf * (1.0f / (float)TLEN)) - 0.5f;
    float hi  = fmaxf(Lf - 1.0f, 0.0f);
    src = fminf(fmaxf(src, 0.0f), hi);
    int   i0 = (int)floorf(src);
    int   i1 = min(i0 + 1, max(L - 1, 0));
    float w  = src - (float)i0;
    const float4* r0 = (const float4*)(x + ((size_t)b * SEQ + i0) * DMODEL);
    const float4* r1 = (const float4*)(x + ((size_t)b * SEQ + i1) * DMODEL);
    float4 v0 = r0[lane], v1 = r1[lane];
    float o[4];
    o[0] = (1.0f - w) * v0.x + w * v1.x;
    o[1] = (1.0f - w) * v0.y + w * v1.y;
    o[2] = (1.0f - w) * v0.z + w * v1.z;
    o[3] = (1.0f - w) * v0.w + w * v1.w;
    size_t base = ((size_t)(b * TLEN + t)) * DMODEL + lane * 4;
    __half2 p0, p1;
    p0.x = __float2half_rn(o[0]); p0.y = __float2half_rn(o[1]);
    p1.x = __float2half_rn(o[2]); p1.y = __float2half_rn(o[3]);
    *(__half2*)(g_a + base)     = p0;
    *(__half2*)(g_a + base + 2) = p1;
}

// ------------------------- fused weight prep (ONE launch) -------------------
__global__ void prep_all_w_kernel(const float* __restrict__ in_w,
                                  const float* __restrict__ wout_w,
                                  const float* __restrict__ win_w,
                                  __half* __restrict__ wdst) {
    __shared__ float t[32][33];
    int bid = blockIdx.x;
    const float* W;
    int srcld, gated, tile;
    size_t dsto;
    if (bid < 64) {
        W = in_w; srcld = 256; gated = 0; dsto = WOFF_IN; tile = bid;
    } else if (bid < 320) {
        int tt = bid - 64, i = tt >> 6;
        W = wout_w + (size_t)i * 65536; srcld = 256; gated = 0;
        dsto = WOFF_WOUT(i); tile = tt & 63;
    } else {
        int tt = bid - 320, i = tt >> 7;
        W = win_w + (size_t)i * 131072; srcld = 512; gated = 1;
        dsto = WOFF_GATE(i); tile = tt & 127;
    }
    int kx = (tile & 7) * 32, py = (tile >> 3) * 32;
    int tx = threadIdx.x, ty = threadIdx.y;
    int p = py + tx;
    int srccol;
    if (gated) {
        int j = p >> 7, r5 = p & 127;
        srccol = j * 64 + (r5 & 63) + ((r5 & 64) ? 256 : 0);
    } else srccol = p;
    t[ty][tx] = W[(size_t)(kx + ty) * srcld + srccol];
    __syncthreads();
    int pp = py + ty, k = kx + tx;
    wdst[dsto + (size_t)pp * KDIM + k] = __float2half_rn(t[tx][ty]);
}

// ------------------------- fused LN + conv -> fp16 --------------------------
__global__ __launch_bounds__(256)
void lnconv_kernel(const float* __restrict__ h,
                   const float* __restrict__ g, const float* __restrict__ bta,
                   const float* __restrict__ w, const float* __restrict__ cbias,
                   __half* __restrict__ oh) {
    __shared__ float sh[36][DMODEL];
    int b = blockIdx.y;
    int t0 = blockIdx.x * 32;
    int warp = threadIdx.x >> 5, lane = threadIdx.x & 31;

    for (int r = warp; r < 36; r += 8) {
        int t = t0 - 2 + r;
        if (t < 0 || t >= TLEN) {
            float4 z = make_float4(0.f, 0.f, 0.f, 0.f);
            ((float4*)sh[r])[lane * 2]     = z;
            ((float4*)sh[r])[lane * 2 + 1] = z;
        } else {
            const float4* p = (const float4*)(h + ((size_t)(b * TLEN + t)) * DMODEL);
            float4 v0 = p[lane * 2], v1 = p[lane * 2 + 1];
            float s  = v0.x + v0.y + v0.z + v0.w + v1.x + v1.y + v1.z + v1.w;
            float sq = v0.x*v0.x + v0.y*v0.y + v0.z*v0.z + v0.w*v0.w
                     + v1.x*v1.x + v1.y*v1.y + v1.z*v1.z + v1.w*v1.w;
            #pragma unroll
            for (int o = 16; o > 0; o >>= 1) {
                s  += __shfl_xor_sync(0xffffffffu, s,  o);
                sq += __shfl_xor_sync(0xffffffffu, sq, o);
            }
            float mu  = s  * (1.0f / (float)DMODEL);
            float var = sq * (1.0f / (float)DMODEL) - mu * mu;
            float rs  = rsqrtf(var + EPSV);
            const float4* gp = (const float4*)g;
            const float4* bp = (const float4*)bta;
            float4 g0 = gp[lane * 2], g1 = gp[lane * 2 + 1];
            float4 b0 = bp[lane * 2], b1 = bp[lane * 2 + 1];
            float4 o0, o1;
            o0.x = (v0.x - mu) * rs * g0.x + b0.x;
            o0.y = (v0.y - mu) * rs * g0.y + b0.y;
            o0.z = (v0.z - mu) * rs * g0.z + b0.z;
            o0.w = (v0.w - mu) * rs * g0.w + b0.w;
            o1.x = (v1.x - mu) * rs * g1.x + b1.x;
            o1.y = (v1.y - mu) * rs * g1.y + b1.y;
            o1.z = (v1.z - mu) * rs * g1.z + b1.z;
            o1.w = (v1.w - mu) * rs * g1.w + b1.w;
            ((float4*)sh[r])[lane * 2]     = o0;
            ((float4*)sh[r])[lane * 2 + 1] = o1;
        }
    }
    __syncthreads();

    int d = threadIdx.x;
    float w0 = w[d * KSZ + 0], w1 = w[d * KSZ + 1], w2 = w[d * KSZ + 2];
    float w3 = w[d * KSZ + 3], w4 = w[d * KSZ + 4];
    float cb = cbias[d];
    float acc[32];
    #pragma unroll
    for (int t = 0; t < 32; t++) {
        float a = cb;
        a = fmaf(w0, sh[t    ][d], a);
        a = fmaf(w1, sh[t + 1][d], a);
        a = fmaf(w2, sh[t + 2][d], a);
        a = fmaf(w3, sh[t + 3][d], a);
        a = fmaf(w4, sh[t + 4][d], a);
        acc[t] = a;
    }
    __syncthreads();
    #pragma unroll
    for (int t = 0; t < 32; t++) sh[t][d] = acc[t];
    __syncthreads();

    size_t rowbase = (size_t)(b * TLEN + t0);
    for (int p = threadIdx.x; p < 32 * 128; p += 256) {
        int r = p >> 7, dp = (p & 127) * 2;
        __half2 ph;
        ph.x = __float2half_rn(sh[r][dp]);
        ph.y = __float2half_rn(sh[r][dp + 1]);
        *(__half2*)(oh + (rowbase + r) * DMODEL + dp) = ph;
    }
}

// ------------------------- warp-per-row final layer norm --------------------
__global__ void ln_warp_kernel(const float* __restrict__ in,
                               const float* __restrict__ g,
                               const float* __restrict__ bta,
                               float* __restrict__ out) {
    int warp = threadIdx.x >> 5, lane = threadIdx.x & 31;
    int m = blockIdx.x * 8 + warp;
    const float4* p = (const float4*)(in + (size_t)m * DMODEL);
    float4 v0 = p[lane * 2], v1 = p[lane * 2 + 1];
    float s  = v0.x + v0.y + v0.z + v0.w + v1.x + v1.y + v1.z + v1.w;
    float sq = v0.x*v0.x + v0.y*v0.y + v0.z*v0.z + v0.w*v0.w
             + v1.x*v1.x + v1.y*v1.y + v1.z*v1.z + v1.w*v1.w;
    #pragma unroll
    for (int o = 16; o > 0; o >>= 1) {
        s  += __shfl_xor_sync(0xffffffffu, s,  o);
        sq += __shfl_xor_sync(0xffffffffu, sq, o);
    }
    float mu  = s  * (1.0f / (float)DMODEL);
    float var = sq * (1.0f / (float)DMODEL) - mu * mu;
    float rs  = rsqrtf(var + EPSV);
    const float4* gp = (const float4*)g;
    const float4* bp = (const float4*)bta;
    float4 g0 = gp[lane * 2], g1 = gp[lane * 2 + 1];
    float4 b0 = bp[lane * 2], b1 = bp[lane * 2 + 1];
    float4 o0, o1;
    o0.x = (v0.x - mu) * rs * g0.x + b0.x;
    o0.y = (v0.y - mu) * rs * g0.y + b0.y;
    o0.z = (v0.z - mu) * rs * g0.z + b0.z;
    o0.w = (v0.w - mu) * rs * g0.w + b0.w;
    o1.x = (v1.x - mu) * rs * g1.x + b1.x;
    o1.y = (v1.y - mu) * rs * g1.y + b1.y;
    o1.z = (v1.z - mu) * rs * g1.z + b1.z;
    o1.w = (v1.w - mu) * rs * g1.w + b1.w;
    ((float4*)(out + (size_t)m * DMODEL))[lane * 2]     = o0;
    ((float4*)(out + (size_t)m * DMODEL))[lane * 2 + 1] = o1;
}

// ------------------------- square fp16 GEMM (R13 config, 64x128, 4 stages) --
#define TS4   80
#define A_T4  (64 * TS4)             // 5120
#define B_T4  (128 * TS4)            // 10240
#define ST4   (A_T4 + B_T4)          // 15360
#define GEMM_SMEM_S (4 * ST4)        // 61440

template<int RES>
__global__ __launch_bounds__(256, 3)
void gemm_sq_kernel(const __half* __restrict__ A,
                    const __half* __restrict__ B,
                    const float* __restrict__ bias, const float* __restrict__ resid,
                    float* __restrict__ outf) {
    extern __shared__ char sm[];
    unsigned sbase = smem_u32(sm);
    const int tid = threadIdx.x, wid = tid >> 5, lane = tid & 31;
    const int m0 = blockIdx.y * 64;
    const int n0p = blockIdx.x * 128;

    const char* A8 = (const char*)A + (size_t)m0 * 512;
    const char* B8 = (const char*)B + (size_t)n0p * 512;

    auto load_stage = [&](int s, int k0) {
        unsigned dst0 = sbase + s * ST4;
        int kbyte = k0 * 2;
        {   int row = tid >> 2, c16 = (tid & 3) * 16;
            CP_ASYNC16(dst0 + row * TS4 + c16,
                       A8 + (size_t)row * 512 + kbyte + c16);
        }
        #pragma unroll
        for (int j = 0; j < 2; j++) {
            int i = tid + j * 256;
            int row = i >> 2, c16 = (i & 3) * 16;
            CP_ASYNC16(dst0 + A_T4 + row * TS4 + c16,
                       B8 + (size_t)row * 512 + kbyte + c16);
        }
        CP_COMMIT();
    };

    load_stage(0, 0);
    load_stage(1, 32);
    load_stage(2, 64);

    const int warpM = wid & 1, warpN = wid >> 1;  // 2 x 4 warps
    float acc[2][4][4];
    #pragma unroll
    for (int mt = 0; mt < 2; mt++)
        #pragma unroll
        for (int nt = 0; nt < 4; nt++)
            #pragma unroll
            for (int e = 0; e < 4; e++) acc[mt][nt][e] = 0.0f;

    const unsigned a_row = warpM * 32 + (lane & 15);
    const unsigned a_cofs = ((lane >> 4) << 3) * 2;
    const unsigned b_row = warpN * 32 + (lane & 7);
    const unsigned b_cofs = (((lane >> 3) & 1) << 3) * 2;

    #pragma unroll 1
    for (int i = 0; i < 8; i++) {
        if (i < 6) { CP_WAIT(2); } else if (i == 6) { CP_WAIT(1); } else { CP_WAIT(0); }
        __syncthreads();
        if (i + 3 < 8) load_stage((i + 3) & 3, (i + 3) * 32);
        unsigned st  = sbase + (i & 3) * ST4;
        unsigned ab  = st;
        unsigned bb  = st + A_T4;
        #pragma unroll
        for (int ks = 0; ks < 2; ks++) {
            unsigned aoff = a_row * TS4 + ks * 32 + a_cofs;
            unsigned boff = b_row * TS4 + ks * 32 + b_cofs;
            unsigned af[2][4];
            unsigned bf[4][2];
            ldsm_x4(af[0], ab + aoff);
            ldsm_x4(af[1], ab + aoff + 16 * TS4);
            #pragma unroll
            for (int nt = 0; nt < 4; nt++)
                ldsm_x2(bf[nt], bb + boff + nt * 8 * TS4);
            #pragma unroll
            for (int nt = 0; nt < 4; nt++)
                #pragma unroll
                for (int mt = 0; mt < 2; mt++)
                    mma16816h(acc[mt][nt], af[mt], bf[nt]);
        }
    }
    __syncthreads();

    float* smf = (float*)sm;   // 64 x 132 staging
    #pragma unroll
    for (int mt = 0; mt < 2; mt++) {
        #pragma unroll
        for (int nt = 0; nt < 4; nt++) {
            int r = warpM * 32 + mt * 16 + (lane >> 2);
            int c = warpN * 32 + nt * 8 + (lane & 3) * 2;
            smf[r * 132 + c]           = acc[mt][nt][0];
            smf[r * 132 + c + 1]       = acc[mt][nt][1];
            smf[(r + 8) * 132 + c]     = acc[mt][nt][2];
            smf[(r + 8) * 132 + c + 1] = acc[mt][nt][3];
        }
    }
    __syncthreads();

    for (int i = tid; i < 64 * 32; i += 256) {
        int row = i >> 5, c4 = (i & 31) * 4;
        float4 o;
        o.x = smf[row * 132 + c4]     + bias[n0p + c4];
        o.y = smf[row * 132 + c4 + 1] + bias[n0p + c4 + 1];
        o.z = smf[row * 132 + c4 + 2] + bias[n0p + c4 + 2];
        o.w = smf[row * 132 + c4 + 3] + bias[n0p + c4 + 3];
        size_t base = (size_t)(m0 + row) * DMODEL + n0p + c4;
        if (RES) {
            float4 rr = *(const float4*)(resid + base);
            o.x += rr.x; o.y += rr.y; o.z += rr.z; o.w += rr.w;
        }
        *(float4*)(outf + base) = o;
    }
}

// ------------------------- gated fp16 GEMM (128 x 256-Brows, 512 thr) -------
// BM=128 rows of A, BROWS=256 prepped weight rows per CTA (covers 128 out
// cols: gate Brows {0-63,128-191}, value {64-127,192-255} locally).
// 3-stage BK=32 ring. Epilogue in two 64-row halves through smem.
#define GTS   80
#define GA_T  (128 * GTS)            // 10240
#define GB_T  (256 * GTS)            // 20480
#define GST   (GA_T + GB_T)          // 30720
#define GEMM_SMEM_G (3 * GST)        // 92160

__global__ __launch_bounds__(512, 1)
void gemm_gated_kernel(const __half* __restrict__ A,
                       const __half* __restrict__ B,
                       const float* __restrict__ bias,
                       __half* __restrict__ outh) {
    extern __shared__ char sm[];
    unsigned sbase = smem_u32(sm);
    const int tid = threadIdx.x, wid = tid >> 5, lane = tid & 31;
    const int m0 = blockIdx.y * 128;
    const int nb = blockIdx.x;          // 0..1

    const char* A8 = (const char*)A + (size_t)m0 * 512;
    const char* B8 = (const char*)B + (size_t)nb * 256 * 512;

    auto load_stage = [&](int s, int k0) {
        unsigned dst0 = sbase + s * GST;
        int kbyte = k0 * 2;
        {   // A: 128 rows x 4 chunks = 512 ops = 1/thread
            int row = tid >> 2, c16 = (tid & 3) * 16;
            CP_ASYNC16(dst0 + row * GTS + c16,
                       A8 + (size_t)row * 512 + kbyte + c16);
        }
        #pragma unroll
        for (int j = 0; j < 2; j++) {   // B: 256 rows x 4 = 1024 ops
            int i = tid + j * 512;
            int row = i >> 2, c16 = (i & 3) * 16;
            CP_ASYNC16(dst0 + GA_T + row * GTS + c16,
                       B8 + (size_t)row * 512 + kbyte + c16);
        }
        CP_COMMIT();
    };

    load_stage(0, 0);
    load_stage(1, 32);

    const int warpM = wid & 3, warpN = wid >> 2;   // 4 x 4 warps, 32x64 tiles
    float acc[2][8][4];
    #pragma unroll
    for (int mt = 0; mt < 2; mt++)
        #pragma unroll
        for (int nt = 0; nt < 8; nt++)
            #pragma unroll
            for (int e = 0; e < 4; e++) acc[mt][nt][e] = 0.0f;

    const unsigned a_row = warpM * 32 + (lane & 15);
    const unsigned a_cofs = ((lane >> 4) << 3) * 2;
    const unsigned b_row = warpN * 64 + (lane & 7);
    const unsigned b_cofs = (((lane >> 3) & 1) << 3) * 2;

    #pragma unroll 1
    for (int i = 0; i < 8; i++) {
        if (i < 7) { CP_WAIT(1); } else { CP_WAIT(0); }
        __syncthreads();
        if (i + 2 < 8) load_stage((i + 2) % 3, (i + 2) * 32);
        unsigned st  = sbase + (i % 3) * GST;
        unsigned ab  = st;
        unsigned bb  = st + GA_T;
        #pragma unroll
        for (int ks = 0; ks < 2; ks++) {
            unsigned aoff = a_row * GTS + ks * 32 + a_cofs;
            unsigned boff = b_row * GTS + ks * 32 + b_cofs;
            unsigned af[2][4];
            unsigned bf[8][2];
            ldsm_x4(af[0], ab + aoff);
            ldsm_x4(af[1], ab + aoff + 16 * GTS);
            #pragma unroll
            for (int nt = 0; nt < 8; nt++)
                ldsm_x2(bf[nt], bb + boff + nt * 8 * GTS);
            #pragma unroll
            for (int nt = 0; nt < 8; nt++)
                #pragma unroll
                for (int mt = 0; mt < 2; mt++)
                    mma16816h(acc[mt][nt], af[mt], bf[nt]);
        }
    }
    __syncthreads();

    // ---- epilogue: two 64-row halves through smem (stride 260 floats) ----
    float* smf = (float*)sm;
    const int outn0 = nb * 128;
    #pragma unroll 1
    for (int h = 0; h < 2; h++) {
        if ((warpM >> 1) == h) {
            #pragma unroll
            for (int mt = 0; mt < 2; mt++) {
                #pragma unroll
                for (int nt = 0; nt < 8; nt++) {
                    int r2 = (warpM & 1) * 32 + mt * 16 + (lane >> 2);
                    int c = warpN * 64 + nt * 8 + (lane & 3) * 2;
                    smf[r2 * 260 + c]           = acc[mt][nt][0];
                    smf[r2 * 260 + c + 1]       = acc[mt][nt][1];
                    smf[(r2 + 8) * 260 + c]     = acc[mt][nt][2];
                    smf[(r2 + 8) * 260 + c + 1] = acc[mt][nt][3];
                }
            }
        }
        __syncthreads();
        for (int i = tid; i < 64 * 64; i += 512) {
            int row = i >> 6, g = (i & 63) * 2;
            int lg = ((g >> 6) << 7) + (g & 63);   // local gate Bcol
            float gg0 = smf[row * 260 + lg]      + bias[outn0 + g];
            float gg1 = smf[row * 260 + lg + 1]  + bias[outn0 + g + 1];
            float vv0 = smf[row * 260 + lg + 64] + bias[256 + outn0 + g];
            float vv1 = smf[row * 260 + lg + 65] + bias[256 + outn0 + g + 1];
            float s0 = 1.0f / (1.0f + expf(-gg0));
            float s1 = 1.0f / (1.0f + expf(-gg1));
            float e0 = 0.5f * vv0 * (1.0f + erff(vv0 * 0.7071067811865476f));
            float e1 = 0.5f * vv1 * (1.0f + erff(vv1 * 0.7071067811865476f));
            __half2 ph;
            ph.x = __float2half_rn(s0 * e0);
            ph.y = __float2half_rn(s1 * e1);
            *(__half2*)(outh + (size_t)(m0 + h * 64 + row) * DMODEL + outn0 + g) = ph;
        }
        __syncthreads();
    }
}

// ------------------------- mask tail ----------------------------------------
__global__ void fill_ones_kernel(float* __restrict__ p, int n) {
    int i = blockIdx.x * blockDim.x + threadIdx.x;
    if (i < n) p[i] = 1.0f;
}

// ---------------------------------------------------------------------------
extern "C" void kernel_launch(void* const* d_in, const int* in_sizes, int n_in,
                              void* d_out, int out_size) {
    const float* x      = (const float*)d_in[0];
    const void*  mask   = d_in[1];
    const float* in_w   = (const float*)d_in[2];
    const float* in_b   = (const float*)d_in[3];
    const float* ln_g   = (const float*)d_in[4];
    const float* ln_b   = (const float*)d_in[5];
    const float* dw_w   = (const float*)d_in[6];
    const float* dw_b   = (const float*)d_in[7];
    const float* win_w  = (const float*)d_in[8];
    const float* win_b  = (const float*)d_in[9];
    const float* wout_w = (const float*)d_in[10];
    const float* wout_b = (const float*)d_in[11];
    const float* fn_g   = (const float*)d_in[12];
    const float* fn_b   = (const float*)d_in[13];
    float* out = (float*)d_out;

    __half *a, *c, *w;
    float *h;
    cudaGetSymbolAddress((void**)&a, g_a);
    cudaGetSymbolAddress((void**)&c, g_c);
    cudaGetSymbolAddress((void**)&w, g_w);
    cudaGetSymbolAddress((void**)&h, g_h);

    cudaFuncSetAttribute((const void*)gemm_sq_kernel<0>,
        cudaFuncAttributeMaxDynamicSharedMemorySize, GEMM_SMEM_S);
    cudaFuncSetAttribute((const void*)gemm_sq_kernel<1>,
        cudaFuncAttributeMaxDynamicSharedMemorySize, GEMM_SMEM_S);
    cudaFuncSetAttribute((const void*)gemm_gated_kernel,
        cudaFuncAttributeMaxDynamicSharedMemorySize, GEMM_SMEM_G);

    // 1) mask dtype detection + lengths (one launch)
    lengths_kernel<<<BATCH, 256>>>((const unsigned char*)mask);

    // 2) fused weight prep (one launch)
    prep_all_w_kernel<<<832, dim3(32, 32)>>>(in_w, wout_w, win_w, w);

    // 3) compress to fp16
    compress_kernel<<<dim3(TLEN / 2, BATCH), 128>>>(x);

    // 4) input projection (grid 2 x 128 = 256 CTAs, R13 config)
    gemm_sq_kernel<0><<<dim3(2, 128), 256, GEMM_SMEM_S>>>(
        a, w + WOFF_IN, in_b, nullptr, h);

    // 5) conv blocks
    for (int i = 0; i < NBLK; i++) {
        lnconv_kernel<<<dim3(TLEN / 32, BATCH), 256>>>(
            h, ln_g + i * DMODEL, ln_b + i * DMODEL,
            dw_w + (size_t)i * DMODEL * KSZ, dw_b + i * DMODEL, a);
        gemm_gated_kernel<<<dim3(2, 64), 512, GEMM_SMEM_G>>>(
            a, w + WOFF_GATE(i), win_b + (size_t)i * 2 * DMODEL, c);
        gemm_sq_kernel<1><<<dim3(2, 128), 256, GEMM_SMEM_S>>>(
            c, w + WOFF_WOUT(i), wout_b + i * DMODEL, h, h);
    }

    // 6) final layer norm -> out
    ln_warp_kernel<<<MROWS / 8, 256>>>(h, fn_g, fn_b, out);

    // 7) comp_mask tail (all True -> 1.0f) if present in out buffer
    int main_elems = MROWS * DMODEL;
    int extra = out_size - main_elems;
    if (extra > 0)
        fill_ones_kernel<<<(extra + 255) / 256, 256>>>(out + main_elems, extra);
}